// round 16
// baseline (speedup 1.0000x reference)
#include <cuda_runtime.h>
#include <cuda_fp16.h>
#include <cstdint>

#define N_SVC  50000
#define N_INST 100000
#define N_NODE 50000
#define HDIM   128
#define ODIM   256
#define NTOT   200000
#define NT16   12544
#define NT16_VALID 12500
#define NT16_ALLOC 13056
#define GCHUNK 148
#define T16_PER_CHUNK 88

// pipeline split: aggpack/gemm
#define SPLIT_TILE 6248        // = 71 * 88
#define GEMM_A_CHUNKS 71
#define GEMM_B_CHUNKS 77

#define E_SC 400000
#define E_IN 100000
#define E_NI 100000
#define E_II 800000
#define E_TOT 1400000

#define NDST 300000
#define SCAN_BLKS 293

// proj fused-grid ranges (rel1 blocks handle BOTH hin and hii)
#define PB0 391                // end of svc
#define PB1 1173               // end of inst
#define PB_TOT 1564            // + node

// ---------------- scratch ----------------
__device__ __half g_hsc[(size_t)N_SVC * HDIM];
__device__ __half g_hin[(size_t)N_INST * HDIM];
__device__ __half g_hni[(size_t)N_NODE * HDIM];
__device__ __half g_hii[(size_t)N_INST * HDIM];
__device__ float g_deg[600000];
__device__ int   g_cnt[600000];
__device__ int   g_off[NDST + 1];
__device__ int   g_cur[NDST];
__device__ int   g_bsum[SCAN_BLKS + 1];
__device__ int   g_elist[E_TOT];
__device__ uint2 g_bt[(size_t)NT16_ALLOC * 512];
__device__ uint2 g_wfr[4][4096];
__device__ uint4 g_awt[(size_t)16 * NT16 * 32];

#define OFF_NS_SC 0
#define OFF_ND_SC 50000
#define OFF_NS_IN 100000
#define OFF_ND_IN 200000
#define OFF_NS_NI 250000
#define OFF_ND_NI 300000
#define OFF_NS_II 400000
#define OFF_ND_II 500000
#define OB_SC 0
#define OB_IN 50000
#define OB_NI 100000
#define OB_II 200000

__device__ __forceinline__ int dmap(int i) {
    if (i < 50000)  return OFF_ND_SC + i;
    if (i < 100000) return OFF_ND_IN + (i - 50000);
    if (i < 200000) return OFF_ND_NI + (i - 100000);
    return OFF_ND_II + (i - 200000);
}

// ---------------- helpers ----------------
__device__ __forceinline__ uint32_t packh2(float a, float b) {
    __half2 h = __floats2half2_rn(a, b);
    return *reinterpret_cast<uint32_t*>(&h);
}

__device__ __forceinline__ void mma_f16(float* c, const uint32_t* a, uint32_t b0, uint32_t b1) {
    asm volatile(
        "mma.sync.aligned.m16n8k16.row.col.f32.f16.f16.f32 "
        "{%0,%1,%2,%3}, {%4,%5,%6,%7}, {%8,%9}, {%0,%1,%2,%3};"
        : "+f"(c[0]), "+f"(c[1]), "+f"(c[2]), "+f"(c[3])
        : "r"(a[0]), "r"(a[1]), "r"(a[2]), "r"(a[3]), "r"(b0), "r"(b1));
}

// ---------------- graph prep ----------------
__global__ void k_zeroi(int* __restrict__ p, int n) {
    int i = blockIdx.x * blockDim.x + threadIdx.x;
    if (i < n) p[i] = 0;
}

__global__ void k_count(const int* __restrict__ svc_src, const int* __restrict__ svc_dst,
                        const int* __restrict__ in_src, const int* __restrict__ in_dst,
                        const int* __restrict__ ni_src, const int* __restrict__ ni_dst,
                        const int* __restrict__ ii_src, const int* __restrict__ ii_dst,
                        int* __restrict__ cnt) {
    int i = blockIdx.x * blockDim.x + threadIdx.x;
    const int* p; int off, j;
    if      (i <  400000) { p = svc_src; off = OFF_NS_SC; j = i; }
    else if (i <  800000) { p = svc_dst; off = OFF_ND_SC; j = i - 400000; }
    else if (i <  900000) { p = in_src;  off = OFF_NS_IN; j = i - 800000; }
    else if (i < 1000000) { p = in_dst;  off = OFF_ND_IN; j = i - 900000; }
    else if (i < 1100000) { p = ni_src;  off = OFF_NS_NI; j = i - 1000000; }
    else if (i < 1200000) { p = ni_dst;  off = OFF_ND_NI; j = i - 1100000; }
    else if (i < 2000000) { p = ii_src;  off = OFF_NS_II; j = i - 1200000; }
    else if (i < 2800000) { p = ii_dst;  off = OFF_ND_II; j = i - 2000000; }
    else return;
    atomicAdd(&cnt[off + __ldg(&p[j])], 1);
}

__global__ void k_norm(const int* __restrict__ cnt, float* __restrict__ deg, int n) {
    int i = blockIdx.x * blockDim.x + threadIdx.x;
    if (i < n) deg[i] = rsqrtf(fmaxf((float)cnt[i], 1.0f));
}

__global__ __launch_bounds__(1024) void k_scanA(const int* __restrict__ cnt,
                                                int* __restrict__ off,
                                                int* __restrict__ bsum) {
    __shared__ int wsum[32];
    int i = blockIdx.x * 1024 + threadIdx.x;
    int lane = threadIdx.x & 31, wid = threadIdx.x >> 5;
    int v = (i < NDST) ? cnt[dmap(i)] : 0;
    int s = v;
#pragma unroll
    for (int d = 1; d < 32; d <<= 1) {
        int t = __shfl_up_sync(0xFFFFFFFFu, s, d);
        if (lane >= d) s += t;
    }
    if (lane == 31) wsum[wid] = s;
    __syncthreads();
    if (wid == 0) {
        int w = wsum[lane];
        int ws = w;
#pragma unroll
        for (int d = 1; d < 32; d <<= 1) {
            int t = __shfl_up_sync(0xFFFFFFFFu, ws, d);
            if (lane >= d) ws += t;
        }
        wsum[lane] = ws - w;
        if (lane == 31) bsum[blockIdx.x] = ws;
    }
    __syncthreads();
    if (i < NDST) off[i] = s - v + wsum[wid];
}

__global__ __launch_bounds__(512) void k_scanB(int* __restrict__ bsum) {
    __shared__ int sh[512];
    int i = threadIdx.x;
    int v = (i < SCAN_BLKS) ? bsum[i] : 0;
    sh[i] = v;
    __syncthreads();
#pragma unroll
    for (int d = 1; d < 512; d <<= 1) {
        int t = (i >= d) ? sh[i - d] : 0;
        __syncthreads();
        sh[i] += t;
        __syncthreads();
    }
    if (i < SCAN_BLKS) bsum[i] = sh[i] - v;
}

__global__ __launch_bounds__(1024) void k_scanC(int* __restrict__ off, int* __restrict__ cur,
                                                const int* __restrict__ bsum) {
    int i = blockIdx.x * 1024 + threadIdx.x;
    if (i < NDST) {
        int o = off[i] + bsum[blockIdx.x];
        off[i] = o;
        cur[i] = o;
    }
    if (i == 0) off[NDST] = E_TOT;
}

__global__ void k_fill(const int* __restrict__ svc_src, const int* __restrict__ svc_dst,
                       const int* __restrict__ in_src, const int* __restrict__ in_dst,
                       const int* __restrict__ ni_src, const int* __restrict__ ni_dst,
                       const int* __restrict__ ii_src, const int* __restrict__ ii_dst,
                       int* __restrict__ cur, int* __restrict__ elist) {
    int i = blockIdx.x * blockDim.x + threadIdx.x;
    int d, s, cb;
    if      (i <  400000) { int j = i;          d = __ldg(&svc_dst[j]); s = __ldg(&svc_src[j]); cb = OB_SC; }
    else if (i <  500000) { int j = i - 400000; d = __ldg(&in_dst[j]);  s = __ldg(&in_src[j]);  cb = OB_IN; }
    else if (i <  600000) { int j = i - 500000; d = __ldg(&ni_dst[j]);  s = __ldg(&ni_src[j]);  cb = OB_NI; }
    else if (i < 1400000) { int j = i - 600000; d = __ldg(&ii_dst[j]);  s = __ldg(&ii_src[j]);  cb = OB_II; }
    else return;
    int p = atomicAdd(&cur[cb + d], 1);
    elist[p] = s;
}

// ---------------- W prep ----------------
__global__ void k_prepW(const float* __restrict__ W0, const float* __restrict__ W1,
                        const float* __restrict__ W2, const float* __restrict__ W3,
                        uint2* __restrict__ wfr) {
    const float* W;
    switch (blockIdx.y) {
        case 0: W = W0; break;
        case 1: W = W1; break;
        case 2: W = W2; break;
        default: W = W3; break;
    }
    int id = blockIdx.x * blockDim.x + threadIdx.x;
    int katom = id >> 9, fid = id & 511;
    int natom = fid >> 5, lane = fid & 31;
    int g = lane >> 2, tig = lane & 3;
    int n = natom * 8 + g;
    int k0 = katom * 16 + 2 * tig;
    uint32_t b0 = packh2(W[k0 * 128 + n], W[(k0 + 1) * 128 + n]);
    uint32_t b1 = packh2(W[(k0 + 8) * 128 + n], W[(k0 + 9) * 128 + n]);
    wfr[blockIdx.y * 4096 + id] = make_uint2(b0, b1);
}

__global__ __launch_bounds__(256) void k_prepA(const float* __restrict__ Wt,
                                               uint4* __restrict__ awt) {
    int wtile = blockIdx.y;
    int tile = blockIdx.x * 8 + (threadIdx.x >> 5);
    int lane = threadIdx.x & 31;
    if (tile >= NT16_VALID) return;
    int g = lane >> 2, tig = lane & 3;
    int r0 = wtile * 16 + g, r1 = r0 + 8;
    size_t k0 = (size_t)tile * 16 + 2 * tig;
    const float* p0 = Wt + (size_t)r0 * NTOT;
    const float* p1 = Wt + (size_t)r1 * NTOT;
    uint32_t a0 = packh2(p0[k0], p0[k0 + 1]);
    uint32_t a1 = packh2(p1[k0], p1[k0 + 1]);
    uint32_t a2 = packh2(p0[k0 + 8], p0[k0 + 9]);
    uint32_t a3 = packh2(p1[k0 + 8], p1[k0 + 9]);
    awt[((size_t)wtile * NT16 + tile) * 32 + lane] = make_uint4(a0, a1, a2, a3);
}

// ---- fused projection; inst blocks compute hin AND hii (X reread hits L1) ----
__global__ __launch_bounds__(256, 2) void k_proj_all(
    const float* __restrict__ Xs, const float* __restrict__ Xi,
    const float* __restrict__ Xn,
    const uint2* __restrict__ wfr,
    __half* __restrict__ hsc, __half* __restrict__ hin,
    __half* __restrict__ hni, __half* __restrict__ hii)
{
    __shared__ uint2 s_w[4096];
    const int b = blockIdx.x;
    int rel0, npass, row0, nrows;
    const float* X;
    __half *H0, *H1 = nullptr;
    if (b < PB0)      { rel0 = 0; npass = 1; row0 = b * 128;         X = Xs; H0 = hsc; nrows = N_SVC; }
    else if (b < PB1) { rel0 = 1; npass = 2; row0 = (b - PB0) * 128; X = Xi; H0 = hin; H1 = hii; nrows = N_INST; }
    else              { rel0 = 2; npass = 1; row0 = (b - PB1) * 128; X = Xn; H0 = hni; nrows = N_NODE; }

    const int tid = threadIdx.x, wid = tid >> 5, lane = tid & 31;
    const int g = lane >> 2, tig = lane & 3;

    const int r0 = row0 + wid * 16 + g;
    const int r1 = r0 + 8;
    const bool v0 = (r0 < nrows), v1 = (r1 < nrows);
    const float* p0 = X + (size_t)r0 * 128;
    const float* p1 = X + (size_t)r1 * 128;
    const float2 z2 = make_float2(0.f, 0.f);

    for (int pass = 0; pass < npass; pass++) {
        int rel = (pass == 0) ? rel0 : 3;
        __half* Hout = (pass == 0) ? H0 : H1;
        if (pass) __syncthreads();   // all reads of s_w from prior pass done
        {
            const uint4* src = (const uint4*)(wfr + rel * 4096);
#pragma unroll
            for (int j = 0; j < 8; j++)
                ((uint4*)s_w)[tid + 256 * j] = src[tid + 256 * j];
        }
        __syncthreads();

        float acc[16][4];
#pragma unroll
        for (int na = 0; na < 16; na++)
#pragma unroll
            for (int q = 0; q < 4; q++) acc[na][q] = 0.f;

#pragma unroll 1
        for (int ka = 0; ka < 8; ka++) {
            int kk = ka * 16 + 2 * tig;
            float2 x00 = v0 ? *(const float2*)(p0 + kk) : z2;
            float2 x01 = v0 ? *(const float2*)(p0 + kk + 8) : z2;
            float2 x10 = v1 ? *(const float2*)(p1 + kk) : z2;
            float2 x11 = v1 ? *(const float2*)(p1 + kk + 8) : z2;
            uint32_t a[4];
            a[0] = packh2(x00.x, x00.y);
            a[1] = packh2(x10.x, x10.y);
            a[2] = packh2(x01.x, x01.y);
            a[3] = packh2(x11.x, x11.y);
#pragma unroll
            for (int na = 0; na < 16; na++) {
                uint2 bb = s_w[(ka * 16 + na) * 32 + lane];
                mma_f16(acc[na], a, bb.x, bb.y);
            }
        }

#pragma unroll
        for (int na = 0; na < 16; na++) {
            int col = na * 8 + 2 * tig;
            if (v0) *(__half2*)(Hout + (size_t)r0 * 128 + col) =
                __floats2half2_rn(acc[na][0], acc[na][1]);
            if (v1) *(__half2*)(Hout + (size_t)r1 * 128 + col) =
                __floats2half2_rn(acc[na][2], acc[na][3]);
        }
    }
}

// ---- fused aggregate + bias + leakyrelu + f16 pack (round-13 core, tbase split) ----
__device__ __forceinline__ void gatherStep(const __half* __restrict__ H,
                                           const float* __restrict__ nsrel,
                                           const int* __restrict__ el,
                                           int i, int lane, float4& acc) {
    int s = __ldg(&el[i]);
    float sc = __ldg(&nsrel[s]);
    uint2 u = *(const uint2*)(H + (size_t)s * 128 + lane * 4);
    float2 f0 = __half22float2(*reinterpret_cast<__half2*>(&u.x));
    float2 f1 = __half22float2(*reinterpret_cast<__half2*>(&u.y));
    acc.x += f0.x * sc; acc.y += f0.y * sc;
    acc.z += f1.x * sc; acc.w += f1.y * sc;
}

__device__ __forceinline__ float4 gatherRow(const __half* __restrict__ H,
                                            const float* __restrict__ nsrel,
                                            const int* __restrict__ el,
                                            int o, int c, int lane) {
    float4 acc = make_float4(0.f, 0.f, 0.f, 0.f);
    int e = o + c;
    int i = o;
    for (; i + 4 <= e; i += 4) {
        int s0 = __ldg(&el[i]);
        int s1 = __ldg(&el[i + 1]);
        int s2 = __ldg(&el[i + 2]);
        int s3 = __ldg(&el[i + 3]);
        float c0 = __ldg(&nsrel[s0]);
        float c1 = __ldg(&nsrel[s1]);
        float c2 = __ldg(&nsrel[s2]);
        float c3 = __ldg(&nsrel[s3]);
        uint2 u0 = *(const uint2*)(H + (size_t)s0 * 128 + lane * 4);
        uint2 u1 = *(const uint2*)(H + (size_t)s1 * 128 + lane * 4);
        uint2 u2 = *(const uint2*)(H + (size_t)s2 * 128 + lane * 4);
        uint2 u3 = *(const uint2*)(H + (size_t)s3 * 128 + lane * 4);
        float2 a0 = __half22float2(*reinterpret_cast<__half2*>(&u0.x));
        float2 a1 = __half22float2(*reinterpret_cast<__half2*>(&u0.y));
        float2 b0 = __half22float2(*reinterpret_cast<__half2*>(&u1.x));
        float2 b1 = __half22float2(*reinterpret_cast<__half2*>(&u1.y));
        float2 d0 = __half22float2(*reinterpret_cast<__half2*>(&u2.x));
        float2 d1 = __half22float2(*reinterpret_cast<__half2*>(&u2.y));
        float2 e0 = __half22float2(*reinterpret_cast<__half2*>(&u3.x));
        float2 e1 = __half22float2(*reinterpret_cast<__half2*>(&u3.y));
        acc.x += a0.x * c0 + b0.x * c1 + d0.x * c2 + e0.x * c3;
        acc.y += a0.y * c0 + b0.y * c1 + d0.y * c2 + e0.y * c3;
        acc.z += a1.x * c0 + b1.x * c1 + d1.x * c2 + e1.x * c3;
        acc.w += a1.y * c0 + b1.y * c1 + d1.y * c2 + e1.y * c3;
    }
    for (; i < e; i++) gatherStep(H, nsrel, el, i, lane, acc);
    return acc;
}

__global__ __launch_bounds__(512) void k_aggpack(
    const float* __restrict__ bsc, const float* __restrict__ bin,
    const float* __restrict__ bni, const float* __restrict__ bii,
    uint2* __restrict__ bt, int tbase)
{
    __shared__ float s[16][128];
    const int t = blockIdx.x + tbase;
    const int wid = threadIdx.x >> 5, lane = threadIdx.x & 31;

    float4 val;
    float b0 = 0.f, b1 = 0.f, b2 = 0.f, b3 = 0.f;
    if (t < 3125) {
        int d = t * 16 + wid;
        float4 a = gatherRow(g_hsc, g_deg + OFF_NS_SC, g_elist,
                             g_off[OB_SC + d], g_cnt[OFF_ND_SC + d], lane);
        float nd = g_deg[OFF_ND_SC + d];
        val = make_float4(a.x * nd, a.y * nd, a.z * nd, a.w * nd);
        b0 = __ldg(&bsc[lane * 4]); b1 = __ldg(&bsc[lane * 4 + 1]);
        b2 = __ldg(&bsc[lane * 4 + 2]); b3 = __ldg(&bsc[lane * 4 + 3]);
    } else if (t < 6250) {
        int d = (t - 3125) * 16 + wid;
        float4 a = gatherRow(g_hin, g_deg + OFF_NS_IN, g_elist,
                             g_off[OB_IN + d], g_cnt[OFF_ND_IN + d], lane);
        float nd = g_deg[OFF_ND_IN + d];
        val = make_float4(a.x * nd, a.y * nd, a.z * nd, a.w * nd);
        b0 = __ldg(&bin[lane * 4]); b1 = __ldg(&bin[lane * 4 + 1]);
        b2 = __ldg(&bin[lane * 4 + 2]); b3 = __ldg(&bin[lane * 4 + 3]);
    } else {
        int d = (t - 6250) * 16 + wid;
        float4 a = gatherRow(g_hni, g_deg + OFF_NS_NI, g_elist,
                             g_off[OB_NI + d], g_cnt[OFF_ND_NI + d], lane);
        float n1 = g_deg[OFF_ND_NI + d];
        float4 c = gatherRow(g_hii, g_deg + OFF_NS_II, g_elist,
                             g_off[OB_II + d], g_cnt[OFF_ND_II + d], lane);
        float n2 = g_deg[OFF_ND_II + d];
        val = make_float4(a.x * n1 + c.x * n2, a.y * n1 + c.y * n2,
                          a.z * n1 + c.z * n2, a.w * n1 + c.w * n2);
        b0 = __ldg(&bni[lane * 4]) + __ldg(&bii[lane * 4]);
        b1 = __ldg(&bni[lane * 4 + 1]) + __ldg(&bii[lane * 4 + 1]);
        b2 = __ldg(&bni[lane * 4 + 2]) + __ldg(&bii[lane * 4 + 2]);
        b3 = __ldg(&bni[lane * 4 + 3]) + __ldg(&bii[lane * 4 + 3]);
    }
    val.x += b0; val.y += b1; val.z += b2; val.w += b3;
    val.x = (val.x >= 0.f) ? val.x : 0.01f * val.x;
    val.y = (val.y >= 0.f) ? val.y : 0.01f * val.y;
    val.z = (val.z >= 0.f) ? val.z : 0.01f * val.z;
    val.w = (val.w >= 0.f) ? val.w : 0.01f * val.w;
    *(float4*)&s[wid][lane * 4] = val;
    __syncthreads();

    if (threadIdx.x < 128) {
        int h = threadIdx.x;
#pragma unroll
        for (int j = 0; j < 4; j++) {
            int id = h + 128 * j;
            int lane2 = id & 31;
            int natom = id >> 5;
            int gg = lane2 >> 2, tig = lane2 & 3;
            int n = natom * 8 + gg;
            uint32_t f0 = packh2(s[2 * tig][n], s[2 * tig + 1][n]);
            uint32_t f1 = packh2(s[2 * tig + 8][n], s[2 * tig + 9][n]);
            bt[(size_t)t * 512 + id] = make_uint2(f0, f1);
        }
    }
}

__global__ void k_init_out(float* __restrict__ out, const float* __restrict__ btot) {
    int i = blockIdx.x * blockDim.x + threadIdx.x;
    if (i < ODIM * HDIM) out[i] = btot[i >> 7];
}

// ---- final GEMM (chunk-base for pipeline split) ----
__global__ __launch_bounds__(256, 2) void k_gemm_mma(const uint4* __restrict__ awt,
                                                     const uint2* __restrict__ bt,
                                                     float* __restrict__ out, int cbase) {
    __shared__ uint2 s_b[4096];
    const int tid = threadIdx.x, wid = tid >> 5, lane = tid & 31;
    const int g = lane >> 2, tig = lane & 3;
    const int chunk = blockIdx.x + cbase, mblk = blockIdx.y;
    const int wtile = mblk * 8 + wid;

    float acc[16][4];
#pragma unroll
    for (int na = 0; na < 16; na++)
#pragma unroll
        for (int q = 0; q < 4; q++) acc[na][q] = 0.f;

    for (int sit = 0; sit < T16_PER_CHUNK / 8; sit++) {
        int tile0 = chunk * T16_PER_CHUNK + sit * 8;
        __syncthreads();
        {
            const uint4* src = (const uint4*)(bt + (size_t)tile0 * 512);
#pragma unroll
            for (int j = 0; j < 8; j++)
                ((uint4*)s_b)[tid + 256 * j] = src[tid + 256 * j];
        }
        __syncthreads();
        if (tile0 >= NT16_VALID) continue;
#pragma unroll 1
        for (int t16 = 0; t16 < 8; t16++) {
            int tile = tile0 + t16;
            if (tile >= NT16_VALID) break;
            uint4 a4 = __ldg(&awt[((size_t)wtile * NT16 + tile) * 32 + lane]);
            uint32_t a[4] = {a4.x, a4.y, a4.z, a4.w};
#pragma unroll
            for (int na = 0; na < 16; na++) {
                uint2 b = s_b[(t16 * 16 + na) * 32 + lane];
                mma_f16(acc[na], a, b.x, b.y);
            }
        }
    }

    const int r0 = mblk * 128 + wid * 16 + g;
    const int r1 = r0 + 8;
#pragma unroll
    for (int na = 0; na < 16; na++) {
        int col = na * 8 + 2 * tig;
        float* d0 = out + (size_t)r0 * 128 + col;
        float* d1 = out + (size_t)r1 * 128 + col;
        asm volatile("red.global.add.v2.f32 [%0], {%1, %2};"
                     :: "l"(d0), "f"(acc[na][0]), "f"(acc[na][1]) : "memory");
        asm volatile("red.global.add.v2.f32 [%0], {%1, %2};"
                     :: "l"(d1), "f"(acc[na][2]), "f"(acc[na][3]) : "memory");
    }
}

// ---------------- host ----------------
extern "C" void kernel_launch(void* const* d_in, const int* in_sizes, int n_in,
                              void* d_out, int out_size) {
    (void)in_sizes; (void)n_in; (void)out_size;
    const float* feat_svc  = (const float*)d_in[0];
    const float* feat_inst = (const float*)d_in[1];
    const float* feat_node = (const float*)d_in[2];
    const int* svc_src = (const int*)d_in[3];
    const int* svc_dst = (const int*)d_in[4];
    const int* in_src  = (const int*)d_in[5];
    const int* in_dst  = (const int*)d_in[6];
    const int* ni_src  = (const int*)d_in[7];
    const int* ni_dst  = (const int*)d_in[8];
    const int* ii_src  = (const int*)d_in[9];
    const int* ii_dst  = (const int*)d_in[10];
    const float* W_sc = (const float*)d_in[11];
    const float* b_sc = (const float*)d_in[12];
    const float* W_in = (const float*)d_in[13];
    const float* b_in = (const float*)d_in[14];
    const float* W_ni = (const float*)d_in[15];
    const float* b_ni = (const float*)d_in[16];
    const float* W_ii = (const float*)d_in[17];
    const float* b_ii = (const float*)d_in[18];
    const float* W_tot = (const float*)d_in[19];
    const float* b_tot = (const float*)d_in[20];
    float* out = (float*)d_out;

    __half *p_hsc, *p_hin, *p_hni, *p_hii;
    float *p_deg;
    int *p_cnt, *p_off, *p_cur, *p_el, *p_bsum;
    uint2 *p_bt, *p_wfr;
    uint4 *p_awt;
    cudaGetSymbolAddress((void**)&p_hsc, g_hsc);
    cudaGetSymbolAddress((void**)&p_hin, g_hin);
    cudaGetSymbolAddress((void**)&p_hni, g_hni);
    cudaGetSymbolAddress((void**)&p_hii, g_hii);
    cudaGetSymbolAddress((void**)&p_deg, g_deg);
    cudaGetSymbolAddress((void**)&p_cnt, g_cnt);
    cudaGetSymbolAddress((void**)&p_off, g_off);
    cudaGetSymbolAddress((void**)&p_cur, g_cur);
    cudaGetSymbolAddress((void**)&p_el,  g_elist);
    cudaGetSymbolAddress((void**)&p_bsum, g_bsum);
    cudaGetSymbolAddress((void**)&p_bt,  g_bt);
    cudaGetSymbolAddress((void**)&p_wfr, g_wfr);
    cudaGetSymbolAddress((void**)&p_awt, g_awt);

    static cudaStream_t s1 = nullptr, s2 = nullptr;
    static cudaEvent_t evRoot = nullptr, evFill = nullptr, evPrepA = nullptr,
                       evProj = nullptr, evAggB = nullptr;
    if (s1 == nullptr) {
        cudaStreamCreateWithFlags(&s1, cudaStreamNonBlocking);
        cudaStreamCreateWithFlags(&s2, cudaStreamNonBlocking);
        cudaEventCreateWithFlags(&evRoot, cudaEventDisableTiming);
        cudaEventCreateWithFlags(&evFill, cudaEventDisableTiming);
        cudaEventCreateWithFlags(&evPrepA, cudaEventDisableTiming);
        cudaEventCreateWithFlags(&evProj, cudaEventDisableTiming);
        cudaEventCreateWithFlags(&evAggB, cudaEventDisableTiming);
    }

    cudaEventRecord(evRoot, 0);

    // s1 branch: graph prep (counts -> norms -> CSR)
    cudaStreamWaitEvent(s1, evRoot, 0);
    k_zeroi<<<(600000 + 255) / 256, 256, 0, s1>>>(p_cnt, 600000);
    k_count<<<(2800000 + 255) / 256, 256, 0, s1>>>(svc_src, svc_dst, in_src, in_dst,
                                                   ni_src, ni_dst, ii_src, ii_dst, p_cnt);
    k_norm<<<(600000 + 255) / 256, 256, 0, s1>>>(p_cnt, p_deg, 600000);
    k_scanA<<<SCAN_BLKS, 1024, 0, s1>>>(p_cnt, p_off, p_bsum);
    k_scanB<<<1, 512, 0, s1>>>(p_bsum);
    k_scanC<<<SCAN_BLKS, 1024, 0, s1>>>(p_off, p_cur, p_bsum);
    k_fill<<<(E_TOT + 255) / 256, 256, 0, s1>>>(svc_src, svc_dst, in_src, in_dst,
                                                ni_src, ni_dst, ii_src, ii_dst, p_cur, p_el);
    cudaEventRecord(evFill, s1);

    // s2 branch: output init + W_tot fp16 A-fragments
    cudaStreamWaitEvent(s2, evRoot, 0);
    k_init_out<<<(ODIM * HDIM + 255) / 256, 256, 0, s2>>>(out, b_tot);
    {
        dim3 ga((NT16_VALID + 7) / 8, 16);
        k_prepA<<<ga, 256, 0, s2>>>(W_tot, p_awt);
    }
    cudaEventRecord(evPrepA, s2);

    // default: W fragments then fused projections
    {
        dim3 gw(16, 4);
        k_prepW<<<gw, 256>>>(W_sc, W_in, W_ni, W_ii, p_wfr);
    }
    k_proj_all<<<PB_TOT, 256>>>(feat_svc, feat_inst, feat_node, p_wfr,
                                p_hsc, p_hin, p_hni, p_hii);
    cudaEventRecord(evProj, 0);

    // s1: aggpack part B (INST-heavy tiles) after proj + fill
    cudaStreamWaitEvent(s1, evProj, 0);
    k_aggpack<<<NT16_VALID - SPLIT_TILE, 512, 0, s1>>>(b_sc, b_in, b_ni, b_ii, p_bt, SPLIT_TILE);
    cudaEventRecord(evAggB, s1);

    // default: aggpack part A, then gemm A (co-runs with aggpack B), then gemm B
    cudaStreamWaitEvent(0, evFill, 0);
    k_aggpack<<<SPLIT_TILE, 512>>>(b_sc, b_in, b_ni, b_ii, p_bt, 0);

    cudaStreamWaitEvent(0, evPrepA, 0);
    {
        dim3 gA(GEMM_A_CHUNKS, 2);
        k_gemm_mma<<<gA, 256>>>(p_awt, p_bt, out, 0);
    }
    cudaStreamWaitEvent(0, evAggB, 0);
    {
        dim3 gB(GEMM_B_CHUNKS, 2);
        k_gemm_mma<<<gB, 256>>>(p_awt, p_bt, out, GEMM_A_CHUNKS);
    }
}

// round 17
// speedup vs baseline: 1.1791x; 1.1791x over previous
#include <cuda_runtime.h>
#include <cuda_fp16.h>
#include <cstdint>

#define N_SVC  50000
#define N_INST 100000
#define N_NODE 50000
#define HDIM   128
#define ODIM   256
#define NTOT   200000
#define NT16   12544
#define NT16_VALID 12500
#define NT16_ALLOC 13056
#define GCHUNK 148
#define T16_PER_CHUNK 88

#define E_SC 400000
#define E_IN 100000
#define E_NI 100000
#define E_II 800000
#define E_TOT 1400000

#define NDST 300000
#define SCAN_BLKS 293

// proj fused-grid block ranges (round-13/15 proven: 4 relations, 1 pass each)
#define PB0 391
#define PB1 1173
#define PB2 1564
#define PB_TOT 2346

// ---------------- scratch ----------------
__device__ __half g_hsc[(size_t)N_SVC * HDIM];
__device__ __half g_hin[(size_t)N_INST * HDIM];
__device__ __half g_hni[(size_t)N_NODE * HDIM];
__device__ __half g_hii[(size_t)N_INST * HDIM];
__device__ float g_deg[600000];
__device__ int   g_cnt[600000];
__device__ int   g_off[NDST + 1];
__device__ int   g_cur[NDST];
__device__ int   g_bsum[SCAN_BLKS + 1];
__device__ int   g_elist[E_TOT];
__device__ uint2 g_bt[(size_t)NT16_ALLOC * 512];
__device__ uint2 g_wfr[4][4096];
__device__ uint4 g_awt[(size_t)16 * NT16 * 32];

#define OFF_NS_SC 0
#define OFF_ND_SC 50000
#define OFF_NS_IN 100000
#define OFF_ND_IN 200000
#define OFF_NS_NI 250000
#define OFF_ND_NI 300000
#define OFF_NS_II 400000
#define OFF_ND_II 500000
#define OB_SC 0
#define OB_IN 50000
#define OB_NI 100000
#define OB_II 200000

__device__ __forceinline__ int dmap(int i) {
    if (i < 50000)  return OFF_ND_SC + i;
    if (i < 100000) return OFF_ND_IN + (i - 50000);
    if (i < 200000) return OFF_ND_NI + (i - 100000);
    return OFF_ND_II + (i - 200000);
}

// ---------------- helpers ----------------
__device__ __forceinline__ uint32_t packh2(float a, float b) {
    __half2 h = __floats2half2_rn(a, b);
    return *reinterpret_cast<uint32_t*>(&h);
}

__device__ __forceinline__ void mma_f16(float* c, const uint32_t* a, uint32_t b0, uint32_t b1) {
    asm volatile(
        "mma.sync.aligned.m16n8k16.row.col.f32.f16.f16.f32 "
        "{%0,%1,%2,%3}, {%4,%5,%6,%7}, {%8,%9}, {%0,%1,%2,%3};"
        : "+f"(c[0]), "+f"(c[1]), "+f"(c[2]), "+f"(c[3])
        : "r"(a[0]), "r"(a[1]), "r"(a[2]), "r"(a[3]), "r"(b0), "r"(b1));
}

// ---------------- graph prep ----------------
__global__ void k_zeroi(int* __restrict__ p, int n) {
    int i = blockIdx.x * blockDim.x + threadIdx.x;
    if (i < n) p[i] = 0;
}

__global__ void k_count(const int* __restrict__ svc_src, const int* __restrict__ svc_dst,
                        const int* __restrict__ in_src, const int* __restrict__ in_dst,
                        const int* __restrict__ ni_src, const int* __restrict__ ni_dst,
                        const int* __restrict__ ii_src, const int* __restrict__ ii_dst,
                        int* __restrict__ cnt) {
    int i = blockIdx.x * blockDim.x + threadIdx.x;
    const int* p; int off, j;
    if      (i <  400000) { p = svc_src; off = OFF_NS_SC; j = i; }
    else if (i <  800000) { p = svc_dst; off = OFF_ND_SC; j = i - 400000; }
    else if (i <  900000) { p = in_src;  off = OFF_NS_IN; j = i - 800000; }
    else if (i < 1000000) { p = in_dst;  off = OFF_ND_IN; j = i - 900000; }
    else if (i < 1100000) { p = ni_src;  off = OFF_NS_NI; j = i - 1000000; }
    else if (i < 1200000) { p = ni_dst;  off = OFF_ND_NI; j = i - 1100000; }
    else if (i < 2000000) { p = ii_src;  off = OFF_NS_II; j = i - 1200000; }
    else if (i < 2800000) { p = ii_dst;  off = OFF_ND_II; j = i - 2000000; }
    else return;
    atomicAdd(&cnt[off + __ldg(&p[j])], 1);
}

__global__ void k_norm(const int* __restrict__ cnt, float* __restrict__ deg, int n) {
    int i = blockIdx.x * blockDim.x + threadIdx.x;
    if (i < n) deg[i] = rsqrtf(fmaxf((float)cnt[i], 1.0f));
}

__global__ __launch_bounds__(1024) void k_scanA(const int* __restrict__ cnt,
                                                int* __restrict__ off,
                                                int* __restrict__ bsum) {
    __shared__ int wsum[32];
    int i = blockIdx.x * 1024 + threadIdx.x;
    int lane = threadIdx.x & 31, wid = threadIdx.x >> 5;
    int v = (i < NDST) ? cnt[dmap(i)] : 0;
    int s = v;
#pragma unroll
    for (int d = 1; d < 32; d <<= 1) {
        int t = __shfl_up_sync(0xFFFFFFFFu, s, d);
        if (lane >= d) s += t;
    }
    if (lane == 31) wsum[wid] = s;
    __syncthreads();
    if (wid == 0) {
        int w = wsum[lane];
        int ws = w;
#pragma unroll
        for (int d = 1; d < 32; d <<= 1) {
            int t = __shfl_up_sync(0xFFFFFFFFu, ws, d);
            if (lane >= d) ws += t;
        }
        wsum[lane] = ws - w;
        if (lane == 31) bsum[blockIdx.x] = ws;
    }
    __syncthreads();
    if (i < NDST) off[i] = s - v + wsum[wid];
}

__global__ __launch_bounds__(512) void k_scanB(int* __restrict__ bsum) {
    __shared__ int sh[512];
    int i = threadIdx.x;
    int v = (i < SCAN_BLKS) ? bsum[i] : 0;
    sh[i] = v;
    __syncthreads();
#pragma unroll
    for (int d = 1; d < 512; d <<= 1) {
        int t = (i >= d) ? sh[i - d] : 0;
        __syncthreads();
        sh[i] += t;
        __syncthreads();
    }
    if (i < SCAN_BLKS) bsum[i] = sh[i] - v;
}

__global__ __launch_bounds__(1024) void k_scanC(int* __restrict__ off, int* __restrict__ cur,
                                                const int* __restrict__ bsum) {
    int i = blockIdx.x * 1024 + threadIdx.x;
    if (i < NDST) {
        int o = off[i] + bsum[blockIdx.x];
        off[i] = o;
        cur[i] = o;
    }
    if (i == 0) off[NDST] = E_TOT;
}

__global__ void k_fill(const int* __restrict__ svc_src, const int* __restrict__ svc_dst,
                       const int* __restrict__ in_src, const int* __restrict__ in_dst,
                       const int* __restrict__ ni_src, const int* __restrict__ ni_dst,
                       const int* __restrict__ ii_src, const int* __restrict__ ii_dst,
                       int* __restrict__ cur, int* __restrict__ elist) {
    int i = blockIdx.x * blockDim.x + threadIdx.x;
    int d, s, cb;
    if      (i <  400000) { int j = i;          d = __ldg(&svc_dst[j]); s = __ldg(&svc_src[j]); cb = OB_SC; }
    else if (i <  500000) { int j = i - 400000; d = __ldg(&in_dst[j]);  s = __ldg(&in_src[j]);  cb = OB_IN; }
    else if (i <  600000) { int j = i - 500000; d = __ldg(&ni_dst[j]);  s = __ldg(&ni_src[j]);  cb = OB_NI; }
    else if (i < 1400000) { int j = i - 600000; d = __ldg(&ii_dst[j]);  s = __ldg(&ii_src[j]);  cb = OB_II; }
    else return;
    int p = atomicAdd(&cur[cb + d], 1);
    elist[p] = s;
}

// ---------------- W prep ----------------
__global__ void k_prepW(const float* __restrict__ W0, const float* __restrict__ W1,
                        const float* __restrict__ W2, const float* __restrict__ W3,
                        uint2* __restrict__ wfr) {
    const float* W;
    switch (blockIdx.y) {
        case 0: W = W0; break;
        case 1: W = W1; break;
        case 2: W = W2; break;
        default: W = W3; break;
    }
    int id = blockIdx.x * blockDim.x + threadIdx.x;
    int katom = id >> 9, fid = id & 511;
    int natom = fid >> 5, lane = fid & 31;
    int g = lane >> 2, tig = lane & 3;
    int n = natom * 8 + g;
    int k0 = katom * 16 + 2 * tig;
    uint32_t b0 = packh2(W[k0 * 128 + n], W[(k0 + 1) * 128 + n]);
    uint32_t b1 = packh2(W[(k0 + 8) * 128 + n], W[(k0 + 9) * 128 + n]);
    wfr[blockIdx.y * 4096 + id] = make_uint2(b0, b1);
}

__global__ __launch_bounds__(256) void k_prepA(const float* __restrict__ Wt,
                                               uint4* __restrict__ awt) {
    int wtile = blockIdx.y;
    int tile = blockIdx.x * 8 + (threadIdx.x >> 5);
    int lane = threadIdx.x & 31;
    if (tile >= NT16_VALID) return;
    int g = lane >> 2, tig = lane & 3;
    int r0 = wtile * 16 + g, r1 = r0 + 8;
    size_t k0 = (size_t)tile * 16 + 2 * tig;
    const float* p0 = Wt + (size_t)r0 * NTOT;
    const float* p1 = Wt + (size_t)r1 * NTOT;
    uint32_t a0 = packh2(p0[k0], p0[k0 + 1]);
    uint32_t a1 = packh2(p1[k0], p1[k0 + 1]);
    uint32_t a2 = packh2(p0[k0 + 8], p0[k0 + 9]);
    uint32_t a3 = packh2(p1[k0 + 8], p1[k0 + 9]);
    awt[((size_t)wtile * NT16 + tile) * 32 + lane] = make_uint4(a0, a1, a2, a3);
}

// ---- fused projection: all 4 relations, one kernel (round-15 proven) ----
__global__ __launch_bounds__(256, 2) void k_proj_all(
    const float* __restrict__ Xs, const float* __restrict__ Xi,
    const float* __restrict__ Xn,
    const uint2* __restrict__ wfr,
    __half* __restrict__ hsc, __half* __restrict__ hin,
    __half* __restrict__ hni, __half* __restrict__ hii)
{
    __shared__ uint2 s_w[4096];
    const int b = blockIdx.x;
    int rel, row0, nrows;
    const float* X;
    __half* Hout;
    if (b < PB0)      { rel = 0; row0 = b * 128;          X = Xs; Hout = hsc; nrows = N_SVC; }
    else if (b < PB1) { rel = 1; row0 = (b - PB0) * 128;  X = Xi; Hout = hin; nrows = N_INST; }
    else if (b < PB2) { rel = 2; row0 = (b - PB1) * 128;  X = Xn; Hout = hni; nrows = N_NODE; }
    else              { rel = 3; row0 = (b - PB2) * 128;  X = Xi; Hout = hii; nrows = N_INST; }

    const int tid = threadIdx.x, wid = tid >> 5, lane = tid & 31;
    const int g = lane >> 2, tig = lane & 3;

    {
        const uint4* src = (const uint4*)(wfr + rel * 4096);
#pragma unroll
        for (int j = 0; j < 8; j++)
            ((uint4*)s_w)[tid + 256 * j] = src[tid + 256 * j];
    }
    __syncthreads();

    const int r0 = row0 + wid * 16 + g;
    const int r1 = r0 + 8;
    const bool v0 = (r0 < nrows), v1 = (r1 < nrows);
    const float* p0 = X + (size_t)r0 * 128;
    const float* p1 = X + (size_t)r1 * 128;

    float acc[16][4];
#pragma unroll
    for (int na = 0; na < 16; na++)
#pragma unroll
        for (int q = 0; q < 4; q++) acc[na][q] = 0.f;

    const float2 z2 = make_float2(0.f, 0.f);
#pragma unroll 1
    for (int ka = 0; ka < 8; ka++) {
        int kk = ka * 16 + 2 * tig;
        float2 x00 = v0 ? *(const float2*)(p0 + kk) : z2;
        float2 x01 = v0 ? *(const float2*)(p0 + kk + 8) : z2;
        float2 x10 = v1 ? *(const float2*)(p1 + kk) : z2;
        float2 x11 = v1 ? *(const float2*)(p1 + kk + 8) : z2;
        uint32_t a[4];
        a[0] = packh2(x00.x, x00.y);
        a[1] = packh2(x10.x, x10.y);
        a[2] = packh2(x01.x, x01.y);
        a[3] = packh2(x11.x, x11.y);
#pragma unroll
        for (int na = 0; na < 16; na++) {
            uint2 bb = s_w[(ka * 16 + na) * 32 + lane];
            mma_f16(acc[na], a, bb.x, bb.y);
        }
    }

#pragma unroll
    for (int na = 0; na < 16; na++) {
        int col = na * 8 + 2 * tig;
        if (v0) *(__half2*)(Hout + (size_t)r0 * 128 + col) =
            __floats2half2_rn(acc[na][0], acc[na][1]);
        if (v1) *(__half2*)(Hout + (size_t)r1 * 128 + col) =
            __floats2half2_rn(acc[na][2], acc[na][3]);
    }
}

// ---- fused aggregate (round-13 core) + bias + leakyrelu + f16 pack ----
// Heavy INST tiles scheduled FIRST (reverse tile order) for LPT wave balance.
__device__ __forceinline__ void gatherStep(const __half* __restrict__ H,
                                           const float* __restrict__ nsrel,
                                           const int* __restrict__ el,
                                           int i, int lane, float4& acc) {
    int s = __ldg(&el[i]);
    float sc = __ldg(&nsrel[s]);
    uint2 u = *(const uint2*)(H + (size_t)s * 128 + lane * 4);
    float2 f0 = __half22float2(*reinterpret_cast<__half2*>(&u.x));
    float2 f1 = __half22float2(*reinterpret_cast<__half2*>(&u.y));
    acc.x += f0.x * sc; acc.y += f0.y * sc;
    acc.z += f1.x * sc; acc.w += f1.y * sc;
}

__device__ __forceinline__ float4 gatherRow(const __half* __restrict__ H,
                                            const float* __restrict__ nsrel,
                                            const int* __restrict__ el,
                                            int o, int c, int lane) {
    float4 acc = make_float4(0.f, 0.f, 0.f, 0.f);
    int e = o + c;
    int i = o;
    for (; i + 4 <= e; i += 4) {
        int s0 = __ldg(&el[i]);
        int s1 = __ldg(&el[i + 1]);
        int s2 = __ldg(&el[i + 2]);
        int s3 = __ldg(&el[i + 3]);
        float c0 = __ldg(&nsrel[s0]);
        float c1 = __ldg(&nsrel[s1]);
        float c2 = __ldg(&nsrel[s2]);
        float c3 = __ldg(&nsrel[s3]);
        uint2 u0 = *(const uint2*)(H + (size_t)s0 * 128 + lane * 4);
        uint2 u1 = *(const uint2*)(H + (size_t)s1 * 128 + lane * 4);
        uint2 u2 = *(const uint2*)(H + (size_t)s2 * 128 + lane * 4);
        uint2 u3 = *(const uint2*)(H + (size_t)s3 * 128 + lane * 4);
        float2 a0 = __half22float2(*reinterpret_cast<__half2*>(&u0.x));
        float2 a1 = __half22float2(*reinterpret_cast<__half2*>(&u0.y));
        float2 b0 = __half22float2(*reinterpret_cast<__half2*>(&u1.x));
        float2 b1 = __half22float2(*reinterpret_cast<__half2*>(&u1.y));
        float2 d0 = __half22float2(*reinterpret_cast<__half2*>(&u2.x));
        float2 d1 = __half22float2(*reinterpret_cast<__half2*>(&u2.y));
        float2 e0 = __half22float2(*reinterpret_cast<__half2*>(&u3.x));
        float2 e1 = __half22float2(*reinterpret_cast<__half2*>(&u3.y));
        acc.x += a0.x * c0 + b0.x * c1 + d0.x * c2 + e0.x * c3;
        acc.y += a0.y * c0 + b0.y * c1 + d0.y * c2 + e0.y * c3;
        acc.z += a1.x * c0 + b1.x * c1 + d1.x * c2 + e1.x * c3;
        acc.w += a1.y * c0 + b1.y * c1 + d1.y * c2 + e1.y * c3;
    }
    for (; i < e; i++) gatherStep(H, nsrel, el, i, lane, acc);
    return acc;
}

__global__ __launch_bounds__(512) void k_aggpack(
    const float* __restrict__ bsc, const float* __restrict__ bin,
    const float* __restrict__ bni, const float* __restrict__ bii,
    uint2* __restrict__ bt)
{
    __shared__ float s[16][128];
    const int t = NT16_VALID - 1 - blockIdx.x;   // reverse order: heavy INST tiles first
    const int wid = threadIdx.x >> 5, lane = threadIdx.x & 31;

    float4 val;
    float b0 = 0.f, b1 = 0.f, b2 = 0.f, b3 = 0.f;
    if (t < 3125) {
        int d = t * 16 + wid;
        float4 a = gatherRow(g_hsc, g_deg + OFF_NS_SC, g_elist,
                             g_off[OB_SC + d], g_cnt[OFF_ND_SC + d], lane);
        float nd = g_deg[OFF_ND_SC + d];
        val = make_float4(a.x * nd, a.y * nd, a.z * nd, a.w * nd);
        b0 = __ldg(&bsc[lane * 4]); b1 = __ldg(&bsc[lane * 4 + 1]);
        b2 = __ldg(&bsc[lane * 4 + 2]); b3 = __ldg(&bsc[lane * 4 + 3]);
    } else if (t < 6250) {
        int d = (t - 3125) * 16 + wid;
        float4 a = gatherRow(g_hin, g_deg + OFF_NS_IN, g_elist,
                             g_off[OB_IN + d], g_cnt[OFF_ND_IN + d], lane);
        float nd = g_deg[OFF_ND_IN + d];
        val = make_float4(a.x * nd, a.y * nd, a.z * nd, a.w * nd);
        b0 = __ldg(&bin[lane * 4]); b1 = __ldg(&bin[lane * 4 + 1]);
        b2 = __ldg(&bin[lane * 4 + 2]); b3 = __ldg(&bin[lane * 4 + 3]);
    } else {
        int d = (t - 6250) * 16 + wid;
        float4 a = gatherRow(g_hni, g_deg + OFF_NS_NI, g_elist,
                             g_off[OB_NI + d], g_cnt[OFF_ND_NI + d], lane);
        float n1 = g_deg[OFF_ND_NI + d];
        float4 c = gatherRow(g_hii, g_deg + OFF_NS_II, g_elist,
                             g_off[OB_II + d], g_cnt[OFF_ND_II + d], lane);
        float n2 = g_deg[OFF_ND_II + d];
        val = make_float4(a.x * n1 + c.x * n2, a.y * n1 + c.y * n2,
                          a.z * n1 + c.z * n2, a.w * n1 + c.w * n2);
        b0 = __ldg(&bni[lane * 4]) + __ldg(&bii[lane * 4]);
        b1 = __ldg(&bni[lane * 4 + 1]) + __ldg(&bii[lane * 4 + 1]);
        b2 = __ldg(&bni[lane * 4 + 2]) + __ldg(&bii[lane * 4 + 2]);
        b3 = __ldg(&bni[lane * 4 + 3]) + __ldg(&bii[lane * 4 + 3]);
    }
    val.x += b0; val.y += b1; val.z += b2; val.w += b3;
    val.x = (val.x >= 0.f) ? val.x : 0.01f * val.x;
    val.y = (val.y >= 0.f) ? val.y : 0.01f * val.y;
    val.z = (val.z >= 0.f) ? val.z : 0.01f * val.z;
    val.w = (val.w >= 0.f) ? val.w : 0.01f * val.w;
    *(float4*)&s[wid][lane * 4] = val;
    __syncthreads();

    if (threadIdx.x < 128) {
        int h = threadIdx.x;
#pragma unroll
        for (int j = 0; j < 4; j++) {
            int id = h + 128 * j;
            int lane2 = id & 31;
            int natom = id >> 5;
            int gg = lane2 >> 2, tig = lane2 & 3;
            int n = natom * 8 + gg;
            uint32_t f0 = packh2(s[2 * tig][n], s[2 * tig + 1][n]);
            uint32_t f1 = packh2(s[2 * tig + 8][n], s[2 * tig + 9][n]);
            bt[(size_t)t * 512 + id] = make_uint2(f0, f1);
        }
    }
}

__global__ void k_init_out(float* __restrict__ out, const float* __restrict__ btot) {
    int i = blockIdx.x * blockDim.x + threadIdx.x;
    if (i < ODIM * HDIM) out[i] = btot[i >> 7];
}

// ---- final GEMM: 148 chunks x 88 tiles, one full wave ----
__global__ __launch_bounds__(256, 2) void k_gemm_mma(const uint4* __restrict__ awt,
                                                     const uint2* __restrict__ bt,
                                                     float* __restrict__ out) {
    __shared__ uint2 s_b[4096];
    const int tid = threadIdx.x, wid = tid >> 5, lane = tid & 31;
    const int g = lane >> 2, tig = lane & 3;
    const int chunk = blockIdx.x, mblk = blockIdx.y;
    const int wtile = mblk * 8 + wid;

    float acc[16][4];
#pragma unroll
    for (int na = 0; na < 16; na++)
#pragma unroll
        for (int q = 0; q < 4; q++) acc[na][q] = 0.f;

    for (int sit = 0; sit < T16_PER_CHUNK / 8; sit++) {
        int tile0 = chunk * T16_PER_CHUNK + sit * 8;
        __syncthreads();
        {
            const uint4* src = (const uint4*)(bt + (size_t)tile0 * 512);
#pragma unroll
            for (int j = 0; j < 8; j++)
                ((uint4*)s_b)[tid + 256 * j] = src[tid + 256 * j];
        }
        __syncthreads();
        if (tile0 >= NT16_VALID) continue;
#pragma unroll 1
        for (int t16 = 0; t16 < 8; t16++) {
            int tile = tile0 + t16;
            if (tile >= NT16_VALID) break;
            uint4 a4 = __ldg(&awt[((size_t)wtile * NT16 + tile) * 32 + lane]);
            uint32_t a[4] = {a4.x, a4.y, a4.z, a4.w};
#pragma unroll
            for (int na = 0; na < 16; na++) {
                uint2 b = s_b[(t16 * 16 + na) * 32 + lane];
                mma_f16(acc[na], a, b.x, b.y);
            }
        }
    }

    const int r0 = mblk * 128 + wid * 16 + g;
    const int r1 = r0 + 8;
#pragma unroll
    for (int na = 0; na < 16; na++) {
        int col = na * 8 + 2 * tig;
        float* d0 = out + (size_t)r0 * 128 + col;
        float* d1 = out + (size_t)r1 * 128 + col;
        asm volatile("red.global.add.v2.f32 [%0], {%1, %2};"
                     :: "l"(d0), "f"(acc[na][0]), "f"(acc[na][1]) : "memory");
        asm volatile("red.global.add.v2.f32 [%0], {%1, %2};"
                     :: "l"(d1), "f"(acc[na][2]), "f"(acc[na][3]) : "memory");
    }
}

// ---------------- host ----------------
extern "C" void kernel_launch(void* const* d_in, const int* in_sizes, int n_in,
                              void* d_out, int out_size) {
    (void)in_sizes; (void)n_in; (void)out_size;
    const float* feat_svc  = (const float*)d_in[0];
    const float* feat_inst = (const float*)d_in[1];
    const float* feat_node = (const float*)d_in[2];
    const int* svc_src = (const int*)d_in[3];
    const int* svc_dst = (const int*)d_in[4];
    const int* in_src  = (const int*)d_in[5];
    const int* in_dst  = (const int*)d_in[6];
    const int* ni_src  = (const int*)d_in[7];
    const int* ni_dst  = (const int*)d_in[8];
    const int* ii_src  = (const int*)d_in[9];
    const int* ii_dst  = (const int*)d_in[10];
    const float* W_sc = (const float*)d_in[11];
    const float* b_sc = (const float*)d_in[12];
    const float* W_in = (const float*)d_in[13];
    const float* b_in = (const float*)d_in[14];
    const float* W_ni = (const float*)d_in[15];
    const float* b_ni = (const float*)d_in[16];
    const float* W_ii = (const float*)d_in[17];
    const float* b_ii = (const float*)d_in[18];
    const float* W_tot = (const float*)d_in[19];
    const float* b_tot = (const float*)d_in[20];
    float* out = (float*)d_out;

    __half *p_hsc, *p_hin, *p_hni, *p_hii;
    float *p_deg;
    int *p_cnt, *p_off, *p_cur, *p_el, *p_bsum;
    uint2 *p_bt, *p_wfr;
    uint4 *p_awt;
    cudaGetSymbolAddress((void**)&p_hsc, g_hsc);
    cudaGetSymbolAddress((void**)&p_hin, g_hin);
    cudaGetSymbolAddress((void**)&p_hni, g_hni);
    cudaGetSymbolAddress((void**)&p_hii, g_hii);
    cudaGetSymbolAddress((void**)&p_deg, g_deg);
    cudaGetSymbolAddress((void**)&p_cnt, g_cnt);
    cudaGetSymbolAddress((void**)&p_off, g_off);
    cudaGetSymbolAddress((void**)&p_cur, g_cur);
    cudaGetSymbolAddress((void**)&p_el,  g_elist);
    cudaGetSymbolAddress((void**)&p_bsum, g_bsum);
    cudaGetSymbolAddress((void**)&p_bt,  g_bt);
    cudaGetSymbolAddress((void**)&p_wfr, g_wfr);
    cudaGetSymbolAddress((void**)&p_awt, g_awt);

    static cudaStream_t s1 = nullptr, s2 = nullptr;
    static cudaEvent_t evRoot = nullptr, evFill = nullptr, evPrepA = nullptr;
    if (s1 == nullptr) {
        cudaStreamCreateWithFlags(&s1, cudaStreamNonBlocking);
        cudaStreamCreateWithFlags(&s2, cudaStreamNonBlocking);
        cudaEventCreateWithFlags(&evRoot, cudaEventDisableTiming);
        cudaEventCreateWithFlags(&evFill, cudaEventDisableTiming);
        cudaEventCreateWithFlags(&evPrepA, cudaEventDisableTiming);
    }

    cudaEventRecord(evRoot, 0);

    // s1 branch: graph prep (counts -> norms -> CSR) — overlaps proj
    cudaStreamWaitEvent(s1, evRoot, 0);
    k_zeroi<<<(600000 + 255) / 256, 256, 0, s1>>>(p_cnt, 600000);
    k_count<<<(2800000 + 255) / 256, 256, 0, s1>>>(svc_src, svc_dst, in_src, in_dst,
                                                   ni_src, ni_dst, ii_src, ii_dst, p_cnt);
    k_norm<<<(600000 + 255) / 256, 256, 0, s1>>>(p_cnt, p_deg, 600000);
    k_scanA<<<SCAN_BLKS, 1024, 0, s1>>>(p_cnt, p_off, p_bsum);
    k_scanB<<<1, 512, 0, s1>>>(p_bsum);
    k_scanC<<<SCAN_BLKS, 1024, 0, s1>>>(p_off, p_cur, p_bsum);
    k_fill<<<(E_TOT + 255) / 256, 256, 0, s1>>>(svc_src, svc_dst, in_src, in_dst,
                                                ni_src, ni_dst, ii_src, ii_dst, p_cur, p_el);
    cudaEventRecord(evFill, s1);

    // s2 branch: output init + W_tot fp16 A-fragments
    cudaStreamWaitEvent(s2, evRoot, 0);
    k_init_out<<<(ODIM * HDIM + 255) / 256, 256, 0, s2>>>(out, b_tot);
    {
        dim3 ga((NT16_VALID + 7) / 8, 16);
        k_prepA<<<ga, 256, 0, s2>>>(W_tot, p_awt);
    }
    cudaEventRecord(evPrepA, s2);

    // default: W fragments then fused projections
    {
        dim3 gw(16, 4);
        k_prepW<<<gw, 256>>>(W_sc, W_in, W_ni, W_ii, p_wfr);
    }
    k_proj_all<<<PB_TOT, 256>>>(feat_svc, feat_inst, feat_node, p_wfr,
                                p_hsc, p_hin, p_hni, p_hii);

    // join CSR branch, aggregate + pack (heavy tiles first), join prepA, GEMM
    cudaStreamWaitEvent(0, evFill, 0);
    k_aggpack<<<NT16_VALID, 512>>>(b_sc, b_in, b_ni, b_ii, p_bt);

    cudaStreamWaitEvent(0, evPrepA, 0);
    dim3 gg(GCHUNK, 2);
    k_gemm_mma<<<gg, 256>>>(p_awt, p_bt, out);
}